// round 13
// baseline (speedup 1.0000x reference)
#include <cuda_runtime.h>
#include <cuda.h>
#include <cuda_bf16.h>
#include <cstdint>

#define BATCH 16
#define CH    512
#define NN    4096
#define EPSF  1e-6f

// ---------------- scratch (device globals; no allocation allowed) ----------------
static __device__ __align__(1024) __nv_bfloat16 g_Vs[(size_t)BATCH * CH * NN];    // [b][c][n]
static __device__ __align__(1024) __nv_bfloat16 g_matbf[(size_t)BATCH * CH * CH]; // [b][c][m]
static __device__ __align__(256) float g_vsum[BATCH * NN];
static __device__ __align__(256) float g_sqin[BATCH * NN];
static __device__ __align__(256) float g_gw[BATCH * NN];
static __device__ __align__(256) float g_tailor[BATCH * CH];

// ---------------- PTX helpers ----------------
__device__ __forceinline__ uint32_t smem_u32(const void* p) {
    uint32_t a;
    asm("{ .reg .u64 t; cvta.to.shared.u64 t, %1; cvt.u32.u64 %0, t; }" : "=r"(a) : "l"(p));
    return a;
}
#define MBAR_INIT(a, c) \
    asm volatile("mbarrier.init.shared.b64 [%0], %1;" :: "r"(a), "r"((uint32_t)(c)) : "memory")
#define MBAR_EXPECT(a, bytes) \
    asm volatile("mbarrier.arrive.expect_tx.shared.b64 _, [%0], %1;" :: "r"(a), "r"((uint32_t)(bytes)) : "memory")

__device__ __forceinline__ void mbar_wait(uint32_t mbar, uint32_t parity) {
    asm volatile(
        "{\n\t.reg .pred P;\n\t"
        "WL_%=:\n\t"
        "mbarrier.try_wait.parity.acquire.cta.shared::cta.b64 P, [%0], %1, 0x989680;\n\t"
        "@P bra.uni WD_%=;\n\t"
        "bra.uni WL_%=;\n\t"
        "WD_%=:\n\t}"
        :: "r"(mbar), "r"(parity) : "memory");
}
__device__ __forceinline__ void tma3d(uint32_t dst, const CUtensorMap* tm, int cx, int cy, int cz, uint32_t mbar) {
    asm volatile(
        "cp.async.bulk.tensor.3d.shared::cta.global.tile.mbarrier::complete_tx::bytes "
        "[%0], [%1, {%2, %3, %4}], [%5];"
        :: "r"(dst), "l"(tm), "r"(cx), "r"(cy), "r"(cz), "r"(mbar) : "memory");
}
__device__ __forceinline__ void ldsm_x4(uint32_t& r0, uint32_t& r1, uint32_t& r2, uint32_t& r3, uint32_t a) {
    asm volatile("ldmatrix.sync.aligned.m8n8.x4.shared.b16 {%0,%1,%2,%3}, [%4];"
                 : "=r"(r0), "=r"(r1), "=r"(r2), "=r"(r3) : "r"(a));
}
__device__ __forceinline__ void ldsm_x4_t(uint32_t& r0, uint32_t& r1, uint32_t& r2, uint32_t& r3, uint32_t a) {
    asm volatile("ldmatrix.sync.aligned.m8n8.x4.trans.shared.b16 {%0,%1,%2,%3}, [%4];"
                 : "=r"(r0), "=r"(r1), "=r"(r2), "=r"(r3) : "r"(a));
}
__device__ __forceinline__ void mma_16816(float* d, const uint32_t* a, uint32_t b0, uint32_t b1) {
    asm volatile("mma.sync.aligned.m16n8k16.row.col.f32.bf16.bf16.f32 "
                 "{%0,%1,%2,%3}, {%4,%5,%6,%7}, {%8,%9}, {%0,%1,%2,%3};"
                 : "+f"(d[0]), "+f"(d[1]), "+f"(d[2]), "+f"(d[3])
                 : "r"(a[0]), "r"(a[1]), "r"(a[2]), "r"(a[3]), "r"(b0), "r"(b1));
}

// ---------------- pipeline constants ----------------
#define STAGES 3
#define STGB   32768            // A 16 KB + B 16 KB per stage
#define BOFF   16384
#define GSMEM  (1024 + STAGES * STGB)   // 99328 -> 2 CTAs/SM
// smem ctrl: full[s] mbarrier at sb + 16 + 8*s ; data at sb + 1024

// ---------------- kernel 1: fused stats + Vs (single DRAM pass over x) ----------------
#define SN 128
#define STATS_SMEM (CH * SN * 2 + 2 * 8 * SN * 4 + SN * 4)  // 139776
__global__ void __launch_bounds__(256) stats_kernel(const float* __restrict__ x) {
    extern __shared__ __align__(16) char sm[];
    __nv_bfloat16* vraw = (__nv_bfloat16*)sm;              // [512][128]
    float* red1 = (float*)(sm + CH * SN * 2);              // [8][128]
    float* red2 = red1 + 8 * SN;                           // [8][128]
    float* ssq = red2 + 8 * SN;                            // [128]
    const int b = blockIdx.y;
    const int n0 = blockIdx.x * SN;
    const int tid = threadIdx.x, lane = tid & 31, w = tid >> 5;
    const float* xb = x + (size_t)b * CH * NN + n0 + lane * 4;

    float4 s1 = make_float4(0.f, 0.f, 0.f, 0.f);
    float4 s2 = make_float4(0.f, 0.f, 0.f, 0.f);
#pragma unroll 4
    for (int c = w; c < CH; c += 8) {
        float4 v = *(const float4*)(xb + (size_t)c * NN);
        s1.x += v.x; s1.y += v.y; s1.z += v.z; s1.w += v.w;
        s2.x += v.x * v.x; s2.y += v.y * v.y; s2.z += v.z * v.z; s2.w += v.w * v.w;
        __nv_bfloat162 p0 = __floats2bfloat162_rn(v.x, v.y);
        __nv_bfloat162 p1 = __floats2bfloat162_rn(v.z, v.w);
        uint2 u;
        u.x = *(const uint32_t*)&p0;
        u.y = *(const uint32_t*)&p1;
        *(uint2*)(vraw + c * SN + lane * 4) = u;
    }
    *(float4*)(red1 + w * SN + lane * 4) = s1;
    *(float4*)(red2 + w * SN + lane * 4) = s2;
    __syncthreads();

    if (tid < SN) {
        float a1 = 0.f, a2 = 0.f;
#pragma unroll
        for (int ww = 0; ww < 8; ww++) { a1 += red1[ww * SN + tid]; a2 += red2[ww * SN + tid]; }
        float inorm = rsqrtf(a2);
        float sqin = sqrtf(inorm);
        int n = n0 + tid;
        g_vsum[b * NN + n] = a1;
        g_sqin[b * NN + n] = sqin;
        g_gw[b * NN + n] = sqin * (a1 * inorm + EPSF);
        ssq[tid] = sqin;
    }
    __syncthreads();

    float4 sq = *(const float4*)(ssq + lane * 4);
    __nv_bfloat16* vs = g_Vs + (size_t)b * CH * NN + n0 + lane * 4;
#pragma unroll 4
    for (int c = w; c < CH; c += 8) {
        uint2 u = *(const uint2*)(vraw + c * SN + lane * 4);
        __nv_bfloat162 p0 = *(const __nv_bfloat162*)&u.x;
        __nv_bfloat162 p1 = *(const __nv_bfloat162*)&u.y;
        float2 f0 = __bfloat1622float2(p0);
        float2 f1 = __bfloat1622float2(p1);
        p0 = __floats2bfloat162_rn(f0.x * sq.x, f0.y * sq.y);
        p1 = __floats2bfloat162_rn(f1.x * sq.z, f1.y * sq.w);
        u.x = *(const uint32_t*)&p0;
        u.y = *(const uint32_t*)&p1;
        *(uint2*)(vs + (size_t)c * NN) = u;
    }
}

// ---------------- kernel 2: GEMM1 (SYRK)  matbf[b] = Vs Vs^T ----------------
// CTA tile 128(c) x 128(m), K=4096.  128 threads: 4 warps of 64x64.  2 CTAs/SM.
__global__ void __launch_bounds__(128, 2) gemm1_tc(const __grid_constant__ CUtensorMap tmA) {
    extern __shared__ __align__(16) char smem[];
    const uint32_t sb = smem_u32(smem);
    const uint32_t data = sb + 1024;
    const int tid = threadIdx.x, lane = tid & 31, wid = tid >> 5;
    const int b = blockIdx.z, c0 = blockIdx.y * 128, m0 = blockIdx.x * 128;
    const int wm = (wid & 1) * 64, wn = (wid >> 1) * 64;

    if (tid == 0)
        for (int s = 0; s < STAGES; s++) MBAR_INIT(sb + 16 + 8 * s, 1);
    __syncthreads();
    if (tid == 0) {
        for (int s = 0; s < STAGES; s++) {
            MBAR_EXPECT(sb + 16 + 8 * s, STGB);
            tma3d(data + s * STGB, &tmA, s * 64, c0, b, sb + 16 + 8 * s);
            tma3d(data + s * STGB + BOFF, &tmA, s * 64, m0, b, sb + 16 + 8 * s);
        }
    }

    float acc[4][8][4];
#pragma unroll
    for (int i = 0; i < 4; i++)
#pragma unroll
        for (int j = 0; j < 8; j++)
#pragma unroll
            for (int k = 0; k < 4; k++) acc[i][j][k] = 0.f;

    const int NCH = NN / 64;  // 64
    int slot = 0, ph = 0;
    for (int kc = 0; kc < NCH; kc++) {
        mbar_wait(sb + 16 + 8 * slot, ph);
        uint32_t Ab = data + slot * STGB;
        uint32_t Bb = Ab + BOFF;
#pragma unroll
        for (int kk = 0; kk < 4; kk++) {
            uint32_t a[4][4], bf[4][4];
            uint32_t cb = (uint32_t)((kk * 16 + (lane >> 4) * 8) * 2);
#pragma unroll
            for (int mi = 0; mi < 4; mi++) {
                int r = wm + mi * 16 + (lane & 15);
                ldsm_x4(a[mi][0], a[mi][1], a[mi][2], a[mi][3],
                        Ab + (uint32_t)(r * 128) + ((((uint32_t)(r & 7)) << 4) ^ cb));
            }
#pragma unroll
            for (int ni = 0; ni < 4; ni++) {
                int r = wn + ni * 16 + (lane & 15);
                ldsm_x4(bf[ni][0], bf[ni][1], bf[ni][2], bf[ni][3],
                        Bb + (uint32_t)(r * 128) + ((((uint32_t)(r & 7)) << 4) ^ cb));
            }
#pragma unroll
            for (int mi = 0; mi < 4; mi++)
#pragma unroll
                for (int ni = 0; ni < 4; ni++) {
                    mma_16816(acc[mi][2 * ni + 0], a[mi], bf[ni][0], bf[ni][2]);
                    mma_16816(acc[mi][2 * ni + 1], a[mi], bf[ni][1], bf[ni][3]);
                }
        }
        __syncthreads();
        int nk = kc + STAGES;
        if (tid == 0 && nk < NCH) {
            MBAR_EXPECT(sb + 16 + 8 * slot, STGB);
            tma3d(data + slot * STGB, &tmA, nk * 64, c0, b, sb + 16 + 8 * slot);
            tma3d(data + slot * STGB + BOFF, &tmA, nk * 64, m0, b, sb + 16 + 8 * slot);
        }
        if (++slot == STAGES) { slot = 0; ph ^= 1; }
    }

    // epilogue: bf16 matbf
    __nv_bfloat16* Mo = g_matbf + (size_t)b * CH * CH;
#pragma unroll
    for (int mi = 0; mi < 4; mi++) {
        int r = c0 + wm + mi * 16 + (lane >> 2);
#pragma unroll
        for (int g = 0; g < 8; g++) {
            int col = m0 + wn + g * 8 + (lane & 3) * 2;
            *(__nv_bfloat162*)(Mo + (size_t)r * CH + col) =
                __floats2bfloat162_rn(acc[mi][g][0], acc[mi][g][1]);
            *(__nv_bfloat162*)(Mo + (size_t)(r + 8) * CH + col) =
                __floats2bfloat162_rn(acc[mi][g][2], acc[mi][g][3]);
        }
    }
}

// ---------------- kernel 3: tailor[b,c] = 1/(N + sum_n Vs[c,n]*gw[n]) ----------------
__global__ void __launch_bounds__(128) tailor_kernel() {
    int b = blockIdx.y, c = blockIdx.x;
    const __nv_bfloat16* vs = g_Vs + (size_t)(b * CH + c) * NN;
    const float* gw = g_gw + b * NN;
    float s = 0.f;
    for (int n = threadIdx.x * 8; n < NN; n += 128 * 8) {
        uint4 pk = *(const uint4*)(vs + n);
        const __nv_bfloat162* p2 = (const __nv_bfloat162*)&pk;
        float4 ga = *(const float4*)(gw + n);
        float4 gb = *(const float4*)(gw + n + 4);
        float2 v0 = __bfloat1622float2(p2[0]);
        float2 v1 = __bfloat1622float2(p2[1]);
        float2 v2 = __bfloat1622float2(p2[2]);
        float2 v3 = __bfloat1622float2(p2[3]);
        s += v0.x * ga.x + v0.y * ga.y + v1.x * ga.z + v1.y * ga.w;
        s += v2.x * gb.x + v2.y * gb.y + v3.x * gb.z + v3.y * gb.w;
    }
    __shared__ float red[4];
#pragma unroll
    for (int o = 16; o > 0; o >>= 1) s += __shfl_down_sync(0xffffffffu, s, o);
    if ((threadIdx.x & 31) == 0) red[threadIdx.x >> 5] = s;
    __syncthreads();
    if (threadIdx.x == 0) {
        s = red[0] + red[1] + red[2] + red[3];
        g_tailor[b * CH + c] = 1.0f / (4096.0f + s);
    }
}

// ---------------- kernel 4: GEMM2 + fused epilogue ----------------
// CTA tile 128(c) x 128(n), K=512.  128 threads: 4 warps of 64x64.  2 CTAs/SM.
__global__ void __launch_bounds__(128, 2) gemm2_tc(const __grid_constant__ CUtensorMap tmA,
                                                   const __grid_constant__ CUtensorMap tmB,
                                                   const float* __restrict__ x,
                                                   const float* __restrict__ gamma,
                                                   float* __restrict__ out) {
    extern __shared__ __align__(16) char smem[];
    const uint32_t sb = smem_u32(smem);
    const uint32_t data = sb + 1024;
    const int tid = threadIdx.x, lane = tid & 31, wid = tid >> 5;
    const int b = blockIdx.z, c0 = blockIdx.y * 128, n0 = blockIdx.x * 128;
    const int wm = (wid & 1) * 64, wn = (wid >> 1) * 64;

    if (tid == 0)
        for (int s = 0; s < STAGES; s++) MBAR_INIT(sb + 16 + 8 * s, 1);
    __syncthreads();
    if (tid == 0) {
        for (int s = 0; s < STAGES; s++) {
            MBAR_EXPECT(sb + 16 + 8 * s, STGB);
            tma3d(data + s * STGB, &tmA, s * 64, c0, b, sb + 16 + 8 * s);
#pragma unroll
            for (int sub = 0; sub < 2; sub++)
                tma3d(data + s * STGB + BOFF + sub * 8192, &tmB, n0 + sub * 64, s * 64, b,
                      sb + 16 + 8 * s);
        }
    }

    float acc[4][8][4];
#pragma unroll
    for (int i = 0; i < 4; i++)
#pragma unroll
        for (int j = 0; j < 8; j++)
#pragma unroll
            for (int k = 0; k < 4; k++) acc[i][j][k] = 0.f;

    const int NCH = CH / 64;  // 8
    int slot = 0, ph = 0;
    for (int kc = 0; kc < NCH; kc++) {
        mbar_wait(sb + 16 + 8 * slot, ph);
        uint32_t Ab = data + slot * STGB;
        uint32_t Bsub = Ab + BOFF + (uint32_t)(wn >> 6) * 8192;
#pragma unroll
        for (int kk = 0; kk < 4; kk++) {
            uint32_t a[4][4], bf[4][4];
            uint32_t cb = (uint32_t)((kk * 16 + (lane >> 4) * 8) * 2);
#pragma unroll
            for (int mi = 0; mi < 4; mi++) {
                int r = wm + mi * 16 + (lane & 15);
                ldsm_x4(a[mi][0], a[mi][1], a[mi][2], a[mi][3],
                        Ab + (uint32_t)(r * 128) + ((((uint32_t)(r & 7)) << 4) ^ cb));
            }
            int kr = kk * 16 + (lane & 15);
            uint32_t brow = Bsub + (uint32_t)(kr * 128);
            uint32_t swz = ((uint32_t)(kr & 7)) << 4;
#pragma unroll
            for (int ni = 0; ni < 4; ni++) {
                uint32_t colb = (uint32_t)((ni * 16 + (lane >> 4) * 8) * 2);
                ldsm_x4_t(bf[ni][0], bf[ni][1], bf[ni][2], bf[ni][3], brow + (swz ^ colb));
            }
#pragma unroll
            for (int mi = 0; mi < 4; mi++)
#pragma unroll
                for (int ni = 0; ni < 4; ni++) {
                    mma_16816(acc[mi][2 * ni + 0], a[mi], bf[ni][0], bf[ni][1]);
                    mma_16816(acc[mi][2 * ni + 1], a[mi], bf[ni][2], bf[ni][3]);
                }
        }
        __syncthreads();
        int nk = kc + STAGES;
        if (tid == 0 && nk < NCH) {
            MBAR_EXPECT(sb + 16 + 8 * slot, STGB);
            tma3d(data + slot * STGB, &tmA, nk * 64, c0, b, sb + 16 + 8 * slot);
#pragma unroll
            for (int sub = 0; sub < 2; sub++)
                tma3d(data + slot * STGB + BOFF + sub * 8192, &tmB, n0 + sub * 64, nk * 64, b,
                      sb + 16 + 8 * slot);
        }
        if (++slot == STAGES) { slot = 0; ph ^= 1; }
    }

    // fused epilogue
    const float gam = gamma[0];
    const float* vsum = g_vsum + b * NN;
    const float* sqin = g_sqin + b * NN;
    const float* tl = g_tailor + b * CH;
    const size_t base = (size_t)b * CH * NN;
#pragma unroll
    for (int mi = 0; mi < 4; mi++) {
        int r = c0 + wm + mi * 16 + (lane >> 2);
        float t0 = gam * tl[r];
        float t1 = gam * tl[r + 8];
#pragma unroll
        for (int g = 0; g < 8; g++) {
            int col = n0 + wn + g * 8 + (lane & 3) * 2;
            float2 vs2 = *(const float2*)(vsum + col);
            float2 sq2 = *(const float2*)(sqin + col);
            size_t i0 = base + (size_t)r * NN + col;
            float2 xv = *(const float2*)(x + i0);
            float2 o;
            o.x = xv.x + t0 * (vs2.x + sq2.x * acc[mi][g][0]);
            o.y = xv.y + t0 * (vs2.y + sq2.y * acc[mi][g][1]);
            *(float2*)(out + i0) = o;
            size_t i1 = i0 + (size_t)8 * NN;
            xv = *(const float2*)(x + i1);
            o.x = xv.x + t1 * (vs2.x + sq2.x * acc[mi][g][2]);
            o.y = xv.y + t1 * (vs2.y + sq2.y * acc[mi][g][3]);
            *(float2*)(out + i1) = o;
        }
    }
}

// ---------------- host: tensor maps + launch ----------------
typedef CUresult (*TmapEncodeFn)(CUtensorMap*, CUtensorMapDataType, cuuint32_t, void*,
                                 const cuuint64_t*, const cuuint64_t*, const cuuint32_t*,
                                 const cuuint32_t*, CUtensorMapInterleave, CUtensorMapSwizzle,
                                 CUtensorMapL2promotion, CUtensorMapFloatOOBfill);

static void mk_tmap(TmapEncodeFn enc, CUtensorMap* tm, void* base,
                    unsigned long long d0, unsigned long long d1, unsigned long long d2,
                    unsigned long long s1, unsigned long long s2,
                    unsigned b0, unsigned b1) {
    cuuint64_t dims[3] = {d0, d1, d2};
    cuuint64_t str[2] = {s1, s2};
    cuuint32_t box[3] = {b0, b1, 1};
    cuuint32_t es[3] = {1, 1, 1};
    enc(tm, CU_TENSOR_MAP_DATA_TYPE_BFLOAT16, 3, base, dims, str, box, es,
        CU_TENSOR_MAP_INTERLEAVE_NONE, CU_TENSOR_MAP_SWIZZLE_128B,
        CU_TENSOR_MAP_L2_PROMOTION_L2_128B, CU_TENSOR_MAP_FLOAT_OOB_FILL_NONE);
}

extern "C" void kernel_launch(void* const* d_in, const int* in_sizes, int n_in,
                              void* d_out, int out_size) {
    (void)in_sizes; (void)n_in; (void)out_size;
    const float* x = (const float*)d_in[0];
    const float* gamma = (const float*)d_in[1];
    float* out = (float*)d_out;

    void* fp = nullptr;
    cudaDriverEntryPointQueryResult qr;
    cudaGetDriverEntryPointByVersion("cuTensorMapEncodeTiled", &fp, 12000, cudaEnableDefault, &qr);
    TmapEncodeFn enc = (TmapEncodeFn)fp;

    void *pVs = nullptr, *pM = nullptr;
    cudaGetSymbolAddress(&pVs, g_Vs);
    cudaGetSymbolAddress(&pM, g_matbf);

    CUtensorMap tA1, tA2, tB2;
    // Vs: [n inner, c, b]; box (64k, 128rows) — used for both operands of gemm1
    mk_tmap(enc, &tA1, pVs, NN, CH, BATCH, (unsigned long long)NN * 2,
            (unsigned long long)CH * NN * 2, 64, 128);
    // matbf: [m inner, c, b]; box (64k, 128c)
    mk_tmap(enc, &tA2, pM, CH, CH, BATCH, (unsigned long long)CH * 2,
            (unsigned long long)CH * CH * 2, 64, 128);
    // Vs as B of gemm2: [n inner, k=c, b]; box (64n, 64k), 2 subtiles/stage
    mk_tmap(enc, &tB2, pVs, NN, CH, BATCH, (unsigned long long)NN * 2,
            (unsigned long long)CH * NN * 2, 64, 64);

    cudaFuncSetAttribute(stats_kernel, cudaFuncAttributeMaxDynamicSharedMemorySize, STATS_SMEM);
    cudaFuncSetAttribute(gemm1_tc, cudaFuncAttributeMaxDynamicSharedMemorySize, GSMEM);
    cudaFuncSetAttribute(gemm2_tc, cudaFuncAttributeMaxDynamicSharedMemorySize, GSMEM);

    stats_kernel<<<dim3(NN / SN, BATCH), 256, STATS_SMEM>>>(x);
    gemm1_tc<<<dim3(4, 4, BATCH), 128, GSMEM>>>(tA1);
    tailor_kernel<<<dim3(CH, BATCH), 128>>>();
    gemm2_tc<<<dim3(32, 4, BATCH), 128, GSMEM>>>(tA2, tB2, x, gamma, out);
}

// round 15
// speedup vs baseline: 1.3188x; 1.3188x over previous
#include <cuda_runtime.h>
#include <cuda.h>
#include <cuda_bf16.h>
#include <cstdint>

#define BATCH 16
#define CH    512
#define NN    4096
#define EPSF  1e-6f

// ---------------- scratch (device globals; no allocation allowed) ----------------
static __device__ __align__(1024) __nv_bfloat16 g_Vs[(size_t)BATCH * CH * NN];    // [b][c][n]
static __device__ __align__(1024) __nv_bfloat16 g_matbf[(size_t)BATCH * CH * CH]; // [b][c][m]
static __device__ __align__(256) float g_vsum[BATCH * NN];
static __device__ __align__(256) float g_sqin[BATCH * NN];
static __device__ __align__(256) float g_gw[BATCH * NN];
static __device__ __align__(256) float g_tailor[BATCH * CH];

// ---------------- PTX helpers ----------------
__device__ __forceinline__ uint32_t smem_u32(const void* p) {
    uint32_t a;
    asm("{ .reg .u64 t; cvta.to.shared.u64 t, %1; cvt.u32.u64 %0, t; }" : "=r"(a) : "l"(p));
    return a;
}
#define MBAR_INIT(a, c) \
    asm volatile("mbarrier.init.shared.b64 [%0], %1;" :: "r"(a), "r"((uint32_t)(c)) : "memory")
#define MBAR_EXPECT(a, bytes) \
    asm volatile("mbarrier.arrive.expect_tx.shared.b64 _, [%0], %1;" :: "r"(a), "r"((uint32_t)(bytes)) : "memory")
#define MBAR_ARRIVE(a) \
    asm volatile("mbarrier.arrive.release.cta.shared::cta.b64 _, [%0];" :: "r"(a) : "memory")

__device__ __forceinline__ void mbar_wait(uint32_t mbar, uint32_t parity) {
    asm volatile(
        "{\n\t.reg .pred P;\n\t"
        "WL_%=:\n\t"
        "mbarrier.try_wait.parity.acquire.cta.shared::cta.b64 P, [%0], %1, 0x989680;\n\t"
        "@P bra.uni WD_%=;\n\t"
        "bra.uni WL_%=;\n\t"
        "WD_%=:\n\t}"
        :: "r"(mbar), "r"(parity) : "memory");
}
__device__ __forceinline__ void tma3d(uint32_t dst, const CUtensorMap* tm, int cx, int cy, int cz, uint32_t mbar) {
    asm volatile(
        "cp.async.bulk.tensor.3d.shared::cta.global.tile.mbarrier::complete_tx::bytes "
        "[%0], [%1, {%2, %3, %4}], [%5];"
        :: "r"(dst), "l"(tm), "r"(cx), "r"(cy), "r"(cz), "r"(mbar) : "memory");
}
__device__ __forceinline__ void ldsm_x4(uint32_t& r0, uint32_t& r1, uint32_t& r2, uint32_t& r3, uint32_t a) {
    asm volatile("ldmatrix.sync.aligned.m8n8.x4.shared.b16 {%0,%1,%2,%3}, [%4];"
                 : "=r"(r0), "=r"(r1), "=r"(r2), "=r"(r3) : "r"(a));
}
__device__ __forceinline__ void ldsm_x4_t(uint32_t& r0, uint32_t& r1, uint32_t& r2, uint32_t& r3, uint32_t a) {
    asm volatile("ldmatrix.sync.aligned.m8n8.x4.trans.shared.b16 {%0,%1,%2,%3}, [%4];"
                 : "=r"(r0), "=r"(r1), "=r"(r2), "=r"(r3) : "r"(a));
}
__device__ __forceinline__ void mma_16816(float* d, const uint32_t* a, uint32_t b0, uint32_t b1) {
    asm volatile("mma.sync.aligned.m16n8k16.row.col.f32.bf16.bf16.f32 "
                 "{%0,%1,%2,%3}, {%4,%5,%6,%7}, {%8,%9}, {%0,%1,%2,%3};"
                 : "+f"(d[0]), "+f"(d[1]), "+f"(d[2]), "+f"(d[3])
                 : "r"(a[0]), "r"(a[1]), "r"(a[2]), "r"(a[3]), "r"(b0), "r"(b1));
}

// ---------------- pipeline constants ----------------
#define STAGES 4
#define STGB   49152            // A 16 KB + B 32 KB per stage
#define BOFF   16384
#define GSMEM  (1024 + STAGES * STGB)   // 197632
// smem ctrl: full[s] mbar at sb + 16 + 16*s ; empty[s] mbar at sb + 24 + 16*s ; data at sb + 1024
#define GTHREADS 288   // 8 compute warps + 1 producer warp

// ---------------- kernel 1: fused stats + Vs (single DRAM pass over x) ----------------
#define SN 128
#define STATS_SMEM (CH * SN * 2 + 2 * 8 * SN * 4 + SN * 4)  // 139776
__global__ void __launch_bounds__(256) stats_kernel(const float* __restrict__ x) {
    extern __shared__ __align__(16) char sm[];
    __nv_bfloat16* vraw = (__nv_bfloat16*)sm;              // [512][128]
    float* red1 = (float*)(sm + CH * SN * 2);              // [8][128]
    float* red2 = red1 + 8 * SN;                           // [8][128]
    float* ssq = red2 + 8 * SN;                            // [128]
    const int b = blockIdx.y;
    const int n0 = blockIdx.x * SN;
    const int tid = threadIdx.x, lane = tid & 31, w = tid >> 5;
    const float* xb = x + (size_t)b * CH * NN + n0 + lane * 4;

    float4 s1 = make_float4(0.f, 0.f, 0.f, 0.f);
    float4 s2 = make_float4(0.f, 0.f, 0.f, 0.f);
#pragma unroll 4
    for (int c = w; c < CH; c += 8) {
        float4 v = *(const float4*)(xb + (size_t)c * NN);
        s1.x += v.x; s1.y += v.y; s1.z += v.z; s1.w += v.w;
        s2.x += v.x * v.x; s2.y += v.y * v.y; s2.z += v.z * v.z; s2.w += v.w * v.w;
        __nv_bfloat162 p0 = __floats2bfloat162_rn(v.x, v.y);
        __nv_bfloat162 p1 = __floats2bfloat162_rn(v.z, v.w);
        uint2 u;
        u.x = *(const uint32_t*)&p0;
        u.y = *(const uint32_t*)&p1;
        *(uint2*)(vraw + c * SN + lane * 4) = u;
    }
    *(float4*)(red1 + w * SN + lane * 4) = s1;
    *(float4*)(red2 + w * SN + lane * 4) = s2;
    __syncthreads();

    if (tid < SN) {
        float a1 = 0.f, a2 = 0.f;
#pragma unroll
        for (int ww = 0; ww < 8; ww++) { a1 += red1[ww * SN + tid]; a2 += red2[ww * SN + tid]; }
        float inorm = rsqrtf(a2);
        float sqin = sqrtf(inorm);
        int n = n0 + tid;
        g_vsum[b * NN + n] = a1;
        g_sqin[b * NN + n] = sqin;
        g_gw[b * NN + n] = sqin * (a1 * inorm + EPSF);
        ssq[tid] = sqin;
    }
    __syncthreads();

    float4 sq = *(const float4*)(ssq + lane * 4);
    __nv_bfloat16* vs = g_Vs + (size_t)b * CH * NN + n0 + lane * 4;
#pragma unroll 4
    for (int c = w; c < CH; c += 8) {
        uint2 u = *(const uint2*)(vraw + c * SN + lane * 4);
        __nv_bfloat162 p0 = *(const __nv_bfloat162*)&u.x;
        __nv_bfloat162 p1 = *(const __nv_bfloat162*)&u.y;
        float2 f0 = __bfloat1622float2(p0);
        float2 f1 = __bfloat1622float2(p1);
        p0 = __floats2bfloat162_rn(f0.x * sq.x, f0.y * sq.y);
        p1 = __floats2bfloat162_rn(f1.x * sq.z, f1.y * sq.w);
        u.x = *(const uint32_t*)&p0;
        u.y = *(const uint32_t*)&p1;
        *(uint2*)(vs + (size_t)c * NN) = u;
    }
}

// ---------------- kernel 2: GEMM1 (SYRK)  matbf[b] = Vs Vs^T ----------------
// CTA tile 128(c) x 256(m), K=4096.  288 threads: 8 consumer warps (64x64) + 1 TMA producer warp.
__global__ void __launch_bounds__(GTHREADS, 1) gemm1_tc(const __grid_constant__ CUtensorMap tmA,
                                                        const __grid_constant__ CUtensorMap tmB) {
    extern __shared__ __align__(16) char smem[];
    const uint32_t sb = smem_u32(smem);
    const uint32_t data = sb + 1024;
    const int tid = threadIdx.x, lane = tid & 31, wid = tid >> 5;
    const int b = blockIdx.z, c0 = blockIdx.y * 128, m0 = blockIdx.x * 256;

    if (tid == 0) {
        for (int s = 0; s < STAGES; s++) {
            MBAR_INIT(sb + 16 + 16 * s, 1);   // full: tx-based
            MBAR_INIT(sb + 24 + 16 * s, 8);   // empty: 8 consumer-warp arrivals
        }
    }
    __syncthreads();

    const int NCH = NN / 64;  // 64

    if (wid == 8) {
        // ---- producer warp ----
        if (lane == 0) {
            for (int kc = 0; kc < NCH; kc++) {
                int slot = kc & 3;
                if (kc >= STAGES) mbar_wait(sb + 24 + 16 * slot, ((kc >> 2) - 1) & 1);
                MBAR_EXPECT(sb + 16 + 16 * slot, STGB);
                tma3d(data + slot * STGB, &tmA, kc * 64, c0, b, sb + 16 + 16 * slot);
                tma3d(data + slot * STGB + BOFF, &tmB, kc * 64, m0, b, sb + 16 + 16 * slot);
            }
        }
        return;
    }

    // ---- consumer warps ----
    const int wm = (wid & 1) * 64, wn = (wid >> 1) * 64;
    float acc[4][8][4];
#pragma unroll
    for (int i = 0; i < 4; i++)
#pragma unroll
        for (int j = 0; j < 8; j++)
#pragma unroll
            for (int k = 0; k < 4; k++) acc[i][j][k] = 0.f;

    for (int kc = 0; kc < NCH; kc++) {
        int slot = kc & 3;
        mbar_wait(sb + 16 + 16 * slot, (kc >> 2) & 1);
        uint32_t Ab = data + slot * STGB;
        uint32_t Bb = Ab + BOFF;
#pragma unroll
        for (int kk = 0; kk < 4; kk++) {
            uint32_t a[4][4], bf[4][4];
            uint32_t cb = (uint32_t)((kk * 16 + (lane >> 4) * 8) * 2);
#pragma unroll
            for (int mi = 0; mi < 4; mi++) {
                int r = wm + mi * 16 + (lane & 15);
                ldsm_x4(a[mi][0], a[mi][1], a[mi][2], a[mi][3],
                        Ab + (uint32_t)(r * 128) + ((((uint32_t)(r & 7)) << 4) ^ cb));
            }
#pragma unroll
            for (int ni = 0; ni < 4; ni++) {
                int r = wn + ni * 16 + (lane & 15);
                ldsm_x4(bf[ni][0], bf[ni][1], bf[ni][2], bf[ni][3],
                        Bb + (uint32_t)(r * 128) + ((((uint32_t)(r & 7)) << 4) ^ cb));
            }
#pragma unroll
            for (int mi = 0; mi < 4; mi++)
#pragma unroll
                for (int ni = 0; ni < 4; ni++) {
                    mma_16816(acc[mi][2 * ni + 0], a[mi], bf[ni][0], bf[ni][2]);
                    mma_16816(acc[mi][2 * ni + 1], a[mi], bf[ni][1], bf[ni][3]);
                }
        }
        if (lane == 0) MBAR_ARRIVE(sb + 24 + 16 * slot);
    }

    // epilogue: bf16 matbf
    __nv_bfloat16* Mo = g_matbf + (size_t)b * CH * CH;
#pragma unroll
    for (int mi = 0; mi < 4; mi++) {
        int r = c0 + wm + mi * 16 + (lane >> 2);
#pragma unroll
        for (int g = 0; g < 8; g++) {
            int col = m0 + wn + g * 8 + (lane & 3) * 2;
            *(__nv_bfloat162*)(Mo + (size_t)r * CH + col) =
                __floats2bfloat162_rn(acc[mi][g][0], acc[mi][g][1]);
            *(__nv_bfloat162*)(Mo + (size_t)(r + 8) * CH + col) =
                __floats2bfloat162_rn(acc[mi][g][2], acc[mi][g][3]);
        }
    }
}

// ---------------- kernel 3: tailor[b,c] = 1/(N + sum_n Vs[c,n]*gw[n]) ----------------
__global__ void __launch_bounds__(128) tailor_kernel() {
    int b = blockIdx.y, c = blockIdx.x;
    const __nv_bfloat16* vs = g_Vs + (size_t)(b * CH + c) * NN;
    const float* gw = g_gw + b * NN;
    float s = 0.f;
    for (int n = threadIdx.x * 8; n < NN; n += 128 * 8) {
        uint4 pk = *(const uint4*)(vs + n);
        const __nv_bfloat162* p2 = (const __nv_bfloat162*)&pk;
        float4 ga = *(const float4*)(gw + n);
        float4 gb = *(const float4*)(gw + n + 4);
        float2 v0 = __bfloat1622float2(p2[0]);
        float2 v1 = __bfloat1622float2(p2[1]);
        float2 v2 = __bfloat1622float2(p2[2]);
        float2 v3 = __bfloat1622float2(p2[3]);
        s += v0.x * ga.x + v0.y * ga.y + v1.x * ga.z + v1.y * ga.w;
        s += v2.x * gb.x + v2.y * gb.y + v3.x * gb.z + v3.y * gb.w;
    }
    __shared__ float red[4];
#pragma unroll
    for (int o = 16; o > 0; o >>= 1) s += __shfl_down_sync(0xffffffffu, s, o);
    if ((threadIdx.x & 31) == 0) red[threadIdx.x >> 5] = s;
    __syncthreads();
    if (threadIdx.x == 0) {
        s = red[0] + red[1] + red[2] + red[3];
        g_tailor[b * CH + c] = 1.0f / (4096.0f + s);
    }
}

// ---------------- kernel 4: GEMM2 + fused epilogue ----------------
// CTA tile 128(c) x 256(n), K=512.  288 threads: 8 consumer warps + 1 TMA producer warp.
__global__ void __launch_bounds__(GTHREADS, 1) gemm2_tc(const __grid_constant__ CUtensorMap tmA,
                                                        const __grid_constant__ CUtensorMap tmB,
                                                        const float* __restrict__ x,
                                                        const float* __restrict__ gamma,
                                                        float* __restrict__ out) {
    extern __shared__ __align__(16) char smem[];
    const uint32_t sb = smem_u32(smem);
    const uint32_t data = sb + 1024;
    const int tid = threadIdx.x, lane = tid & 31, wid = tid >> 5;
    const int b = blockIdx.z, c0 = blockIdx.y * 128, n0 = blockIdx.x * 256;

    if (tid == 0) {
        for (int s = 0; s < STAGES; s++) {
            MBAR_INIT(sb + 16 + 16 * s, 1);
            MBAR_INIT(sb + 24 + 16 * s, 8);
        }
    }
    __syncthreads();

    const int NCH = CH / 64;  // 8

    if (wid == 8) {
        if (lane == 0) {
            for (int kc = 0; kc < NCH; kc++) {
                int slot = kc & 3;
                if (kc >= STAGES) mbar_wait(sb + 24 + 16 * slot, ((kc >> 2) - 1) & 1);
                MBAR_EXPECT(sb + 16 + 16 * slot, STGB);
                tma3d(data + slot * STGB, &tmA, kc * 64, c0, b, sb + 16 + 16 * slot);
#pragma unroll
                for (int sub = 0; sub < 4; sub++)
                    tma3d(data + slot * STGB + BOFF + sub * 8192, &tmB, n0 + sub * 64, kc * 64, b,
                          sb + 16 + 16 * slot);
            }
        }
        return;
    }

    const int wm = (wid & 1) * 64, wn = (wid >> 1) * 64;
    float acc[4][8][4];
#pragma unroll
    for (int i = 0; i < 4; i++)
#pragma unroll
        for (int j = 0; j < 8; j++)
#pragma unroll
            for (int k = 0; k < 4; k++) acc[i][j][k] = 0.f;

    for (int kc = 0; kc < NCH; kc++) {
        int slot = kc & 3;
        mbar_wait(sb + 16 + 16 * slot, (kc >> 2) & 1);
        uint32_t Ab = data + slot * STGB;
        uint32_t Bsub = Ab + BOFF + (uint32_t)(wn >> 6) * 8192;
#pragma unroll
        for (int kk = 0; kk < 4; kk++) {
            uint32_t a[4][4], bf[4][4];
            uint32_t cb = (uint32_t)((kk * 16 + (lane >> 4) * 8) * 2);
#pragma unroll
            for (int mi = 0; mi < 4; mi++) {
                int r = wm + mi * 16 + (lane & 15);
                ldsm_x4(a[mi][0], a[mi][1], a[mi][2], a[mi][3],
                        Ab + (uint32_t)(r * 128) + ((((uint32_t)(r & 7)) << 4) ^ cb));
            }
            int kr = kk * 16 + (lane & 15);
            uint32_t brow = Bsub + (uint32_t)(kr * 128);
            uint32_t swz = ((uint32_t)(kr & 7)) << 4;
#pragma unroll
            for (int ni = 0; ni < 4; ni++) {
                uint32_t colb = (uint32_t)((ni * 16 + (lane >> 4) * 8) * 2);
                ldsm_x4_t(bf[ni][0], bf[ni][1], bf[ni][2], bf[ni][3], brow + (swz ^ colb));
            }
#pragma unroll
            for (int mi = 0; mi < 4; mi++)
#pragma unroll
                for (int ni = 0; ni < 4; ni++) {
                    mma_16816(acc[mi][2 * ni + 0], a[mi], bf[ni][0], bf[ni][1]);
                    mma_16816(acc[mi][2 * ni + 1], a[mi], bf[ni][2], bf[ni][3]);
                }
        }
        if (lane == 0) MBAR_ARRIVE(sb + 24 + 16 * slot);
    }

    // fused epilogue
    const float gam = gamma[0];
    const float* vsum = g_vsum + b * NN;
    const float* sqin = g_sqin + b * NN;
    const float* tl = g_tailor + b * CH;
    const size_t base = (size_t)b * CH * NN;
#pragma unroll
    for (int mi = 0; mi < 4; mi++) {
        int r = c0 + wm + mi * 16 + (lane >> 2);
        float t0 = gam * tl[r];
        float t1 = gam * tl[r + 8];
#pragma unroll
        for (int g = 0; g < 8; g++) {
            int col = n0 + wn + g * 8 + (lane & 3) * 2;
            float2 vs2 = *(const float2*)(vsum + col);
            float2 sq2 = *(const float2*)(sqin + col);
            size_t i0 = base + (size_t)r * NN + col;
            float2 xv = *(const float2*)(x + i0);
            float2 o;
            o.x = xv.x + t0 * (vs2.x + sq2.x * acc[mi][g][0]);
            o.y = xv.y + t0 * (vs2.y + sq2.y * acc[mi][g][1]);
            *(float2*)(out + i0) = o;
            size_t i1 = i0 + (size_t)8 * NN;
            xv = *(const float2*)(x + i1);
            o.x = xv.x + t1 * (vs2.x + sq2.x * acc[mi][g][2]);
            o.y = xv.y + t1 * (vs2.y + sq2.y * acc[mi][g][3]);
            *(float2*)(out + i1) = o;
        }
    }
}

// ---------------- host: tensor maps + launch ----------------
typedef CUresult (*TmapEncodeFn)(CUtensorMap*, CUtensorMapDataType, cuuint32_t, void*,
                                 const cuuint64_t*, const cuuint64_t*, const cuuint32_t*,
                                 const cuuint32_t*, CUtensorMapInterleave, CUtensorMapSwizzle,
                                 CUtensorMapL2promotion, CUtensorMapFloatOOBfill);

static void mk_tmap(TmapEncodeFn enc, CUtensorMap* tm, void* base,
                    unsigned long long d0, unsigned long long d1, unsigned long long d2,
                    unsigned long long s1, unsigned long long s2,
                    unsigned b0, unsigned b1) {
    cuuint64_t dims[3] = {d0, d1, d2};
    cuuint64_t str[2] = {s1, s2};
    cuuint32_t box[3] = {b0, b1, 1};
    cuuint32_t es[3] = {1, 1, 1};
    enc(tm, CU_TENSOR_MAP_DATA_TYPE_BFLOAT16, 3, base, dims, str, box, es,
        CU_TENSOR_MAP_INTERLEAVE_NONE, CU_TENSOR_MAP_SWIZZLE_128B,
        CU_TENSOR_MAP_L2_PROMOTION_L2_128B, CU_TENSOR_MAP_FLOAT_OOB_FILL_NONE);
}

extern "C" void kernel_launch(void* const* d_in, const int* in_sizes, int n_in,
                              void* d_out, int out_size) {
    (void)in_sizes; (void)n_in; (void)out_size;
    const float* x = (const float*)d_in[0];
    const float* gamma = (const float*)d_in[1];
    float* out = (float*)d_out;

    void* fp = nullptr;
    cudaDriverEntryPointQueryResult qr;
    cudaGetDriverEntryPointByVersion("cuTensorMapEncodeTiled", &fp, 12000, cudaEnableDefault, &qr);
    TmapEncodeFn enc = (TmapEncodeFn)fp;

    void *pVs = nullptr, *pM = nullptr;
    cudaGetSymbolAddress(&pVs, g_Vs);
    cudaGetSymbolAddress(&pM, g_matbf);

    CUtensorMap tA1, tB1, tA2, tB2;
    mk_tmap(enc, &tA1, pVs, NN, CH, BATCH, (unsigned long long)NN * 2,
            (unsigned long long)CH * NN * 2, 64, 128);
    mk_tmap(enc, &tB1, pVs, NN, CH, BATCH, (unsigned long long)NN * 2,
            (unsigned long long)CH * NN * 2, 64, 256);
    mk_tmap(enc, &tA2, pM, CH, CH, BATCH, (unsigned long long)CH * 2,
            (unsigned long long)CH * CH * 2, 64, 128);
    mk_tmap(enc, &tB2, pVs, NN, CH, BATCH, (unsigned long long)NN * 2,
            (unsigned long long)CH * NN * 2, 64, 64);

    cudaFuncSetAttribute(stats_kernel, cudaFuncAttributeMaxDynamicSharedMemorySize, STATS_SMEM);
    cudaFuncSetAttribute(gemm1_tc, cudaFuncAttributeMaxDynamicSharedMemorySize, GSMEM);
    cudaFuncSetAttribute(gemm2_tc, cudaFuncAttributeMaxDynamicSharedMemorySize, GSMEM);

    stats_kernel<<<dim3(NN / SN, BATCH), 256, STATS_SMEM>>>(x);
    gemm1_tc<<<dim3(2, 4, BATCH), GTHREADS, GSMEM>>>(tA1, tB1);
    tailor_kernel<<<dim3(CH, BATCH), 128>>>();
    gemm2_tc<<<dim3(16, 4, BATCH), GTHREADS, GSMEM>>>(tA2, tB2, x, gamma, out);
}

// round 17
// speedup vs baseline: 1.7030x; 1.2913x over previous
#include <cuda_runtime.h>
#include <cuda.h>
#include <cuda_bf16.h>
#include <cstdint>

#define BATCH 16
#define CH    512
#define NN    4096
#define EPSF  1e-6f

// ---------------- scratch (device globals; no allocation allowed) ----------------
static __device__ __align__(1024) __nv_bfloat16 g_Vs[(size_t)BATCH * CH * NN];    // [b][c][n]
static __device__ __align__(1024) __nv_bfloat16 g_matbf[(size_t)BATCH * CH * CH]; // [b][c][m]
static __device__ __align__(256) float g_vsum[BATCH * NN];
static __device__ __align__(256) float g_sqin[BATCH * NN];
static __device__ __align__(256) float g_tpart[(size_t)BATCH * 64 * CH];          // [b][nb][c]
static __device__ __align__(256) float g_tailor[BATCH * CH];

// ---------------- PTX helpers ----------------
__device__ __forceinline__ uint32_t smem_u32(const void* p) {
    uint32_t a;
    asm("{ .reg .u64 t; cvta.to.shared.u64 t, %1; cvt.u32.u64 %0, t; }" : "=r"(a) : "l"(p));
    return a;
}
#define MBAR_INIT(a, c) \
    asm volatile("mbarrier.init.shared.b64 [%0], %1;" :: "r"(a), "r"((uint32_t)(c)) : "memory")
#define MBAR_EXPECT(a, bytes) \
    asm volatile("mbarrier.arrive.expect_tx.shared.b64 _, [%0], %1;" :: "r"(a), "r"((uint32_t)(bytes)) : "memory")
#define MBAR_ARRIVE(a) \
    asm volatile("mbarrier.arrive.release.cta.shared::cta.b64 _, [%0];" :: "r"(a) : "memory")

__device__ __forceinline__ void mbar_wait(uint32_t mbar, uint32_t parity) {
    asm volatile(
        "{\n\t.reg .pred P;\n\t"
        "WL_%=:\n\t"
        "mbarrier.try_wait.parity.acquire.cta.shared::cta.b64 P, [%0], %1, 0x989680;\n\t"
        "@P bra.uni WD_%=;\n\t"
        "bra.uni WL_%=;\n\t"
        "WD_%=:\n\t}"
        :: "r"(mbar), "r"(parity) : "memory");
}
__device__ __forceinline__ void tma3d(uint32_t dst, const CUtensorMap* tm, int cx, int cy, int cz, uint32_t mbar) {
    asm volatile(
        "cp.async.bulk.tensor.3d.shared::cta.global.tile.mbarrier::complete_tx::bytes "
        "[%0], [%1, {%2, %3, %4}], [%5];"
        :: "r"(dst), "l"(tm), "r"(cx), "r"(cy), "r"(cz), "r"(mbar) : "memory");
}
__device__ __forceinline__ void ldsm_x4(uint32_t& r0, uint32_t& r1, uint32_t& r2, uint32_t& r3, uint32_t a) {
    asm volatile("ldmatrix.sync.aligned.m8n8.x4.shared.b16 {%0,%1,%2,%3}, [%4];"
                 : "=r"(r0), "=r"(r1), "=r"(r2), "=r"(r3) : "r"(a));
}
__device__ __forceinline__ void ldsm_x4_t(uint32_t& r0, uint32_t& r1, uint32_t& r2, uint32_t& r3, uint32_t a) {
    asm volatile("ldmatrix.sync.aligned.m8n8.x4.trans.shared.b16 {%0,%1,%2,%3}, [%4];"
                 : "=r"(r0), "=r"(r1), "=r"(r2), "=r"(r3) : "r"(a));
}
__device__ __forceinline__ void mma_16816(float* d, const uint32_t* a, uint32_t b0, uint32_t b1) {
    asm volatile("mma.sync.aligned.m16n8k16.row.col.f32.bf16.bf16.f32 "
                 "{%0,%1,%2,%3}, {%4,%5,%6,%7}, {%8,%9}, {%0,%1,%2,%3};"
                 : "+f"(d[0]), "+f"(d[1]), "+f"(d[2]), "+f"(d[3])
                 : "r"(a[0]), "r"(a[1]), "r"(a[2]), "r"(a[3]), "r"(b0), "r"(b1));
}

// ---------------- pipeline constants ----------------
#define STAGES 4
#define STGB   49152            // A 16 KB + B 32 KB per stage
#define BOFF   16384
#define GSMEM  (1024 + STAGES * STGB)   // 197632
// smem ctrl: full[s] mbar at sb + 16 + 16*s ; empty[s] mbar at sb + 24 + 16*s ; data at sb + 1024
#define GTHREADS 288   // 8 compute warps + 1 producer warp

// ---------------- kernel 1: fused stats + Vs + tailor partials ----------------
// 64-wide n-tiles -> ~74 KB smem -> 3 CTAs/SM.
#define SN 64
#define STATS_SMEM (CH * SN * 2 + 2 * 16 * SN * 4 + 2 * SN * 4)  // 74240
__global__ void __launch_bounds__(256) stats_kernel(const float* __restrict__ x) {
    extern __shared__ __align__(16) char sm[];
    __nv_bfloat16* vraw = (__nv_bfloat16*)sm;              // [512][64]
    float* red1 = (float*)(sm + CH * SN * 2);              // [16][64]
    float* red2 = red1 + 16 * SN;                          // [16][64]
    float* ssq = red2 + 16 * SN;                           // [64]
    float* sgw = ssq + SN;                                 // [64]
    const int b = blockIdx.y, nb = blockIdx.x;
    const int n0 = nb * SN;
    const int tid = threadIdx.x;
    const int g = tid >> 4, l4 = tid & 15, col = l4 * 4;
    const float* xb = x + (size_t)b * CH * NN + n0 + col;

    float4 s1 = make_float4(0.f, 0.f, 0.f, 0.f);
    float4 s2 = make_float4(0.f, 0.f, 0.f, 0.f);
#pragma unroll 4
    for (int c = g; c < CH; c += 16) {
        float4 v = *(const float4*)(xb + (size_t)c * NN);
        s1.x += v.x; s1.y += v.y; s1.z += v.z; s1.w += v.w;
        s2.x += v.x * v.x; s2.y += v.y * v.y; s2.z += v.z * v.z; s2.w += v.w * v.w;
        __nv_bfloat162 p0 = __floats2bfloat162_rn(v.x, v.y);
        __nv_bfloat162 p1 = __floats2bfloat162_rn(v.z, v.w);
        uint2 u;
        u.x = *(const uint32_t*)&p0;
        u.y = *(const uint32_t*)&p1;
        *(uint2*)(vraw + c * SN + col) = u;
    }
    *(float4*)(red1 + g * SN + col) = s1;
    *(float4*)(red2 + g * SN + col) = s2;
    __syncthreads();

    if (tid < SN) {
        float a1 = 0.f, a2 = 0.f;
#pragma unroll
        for (int ww = 0; ww < 16; ww++) { a1 += red1[ww * SN + tid]; a2 += red2[ww * SN + tid]; }
        float inorm = rsqrtf(a2);
        float sqin = sqrtf(inorm);
        int n = n0 + tid;
        g_vsum[b * NN + n] = a1;
        g_sqin[b * NN + n] = sqin;
        ssq[tid] = sqin;
        sgw[tid] = sqin * (a1 * inorm + EPSF);
    }
    __syncthreads();

    float4 sq = *(const float4*)(ssq + col);
    float4 gw4 = *(const float4*)(sgw + col);
    __nv_bfloat16* vs = g_Vs + (size_t)b * CH * NN + n0 + col;
    float* tp = g_tpart + ((size_t)b * 64 + nb) * CH;
#pragma unroll 4
    for (int c = g; c < CH; c += 16) {
        uint2 u = *(const uint2*)(vraw + c * SN + col);
        __nv_bfloat162 p0 = *(const __nv_bfloat162*)&u.x;
        __nv_bfloat162 p1 = *(const __nv_bfloat162*)&u.y;
        float2 f0 = __bfloat1622float2(p0);
        float2 f1 = __bfloat1622float2(p1);
        p0 = __floats2bfloat162_rn(f0.x * sq.x, f0.y * sq.y);
        p1 = __floats2bfloat162_rn(f1.x * sq.z, f1.y * sq.w);
        u.x = *(const uint32_t*)&p0;
        u.y = *(const uint32_t*)&p1;
        *(uint2*)(vs + (size_t)c * NN) = u;
        // tailor partial from bf16-rounded Vs
        float2 r0 = __bfloat1622float2(p0);
        float2 r1 = __bfloat1622float2(p1);
        float part = r0.x * gw4.x + r0.y * gw4.y + r1.x * gw4.z + r1.y * gw4.w;
        part += __shfl_down_sync(0xffffffffu, part, 8, 16);
        part += __shfl_down_sync(0xffffffffu, part, 4, 16);
        part += __shfl_down_sync(0xffffffffu, part, 2, 16);
        part += __shfl_down_sync(0xffffffffu, part, 1, 16);
        if (l4 == 0) tp[c] = part;
    }
}

// ---------------- kernel 1b: tailor reduce  g_tailor = 1/(N + sum_nb tpart) ----------------
__global__ void __launch_bounds__(512) tailor_reduce() {
    const int b = blockIdx.x, c = threadIdx.x;
    const float* tp = g_tpart + (size_t)b * 64 * CH + c;
    float s = 0.f;
#pragma unroll 8
    for (int nb = 0; nb < 64; nb++) s += tp[(size_t)nb * CH];
    g_tailor[b * CH + c] = 1.0f / (4096.0f + s);
}

// ---------------- kernel 2: GEMM1 (SYRK)  matbf[b] = Vs Vs^T ----------------
// CTA tile 128(c) x 256(m), K=4096.  288 threads: 8 consumers (64x64) + 1 TMA producer.
__global__ void __launch_bounds__(GTHREADS, 1) gemm1_tc(const __grid_constant__ CUtensorMap tmA,
                                                        const __grid_constant__ CUtensorMap tmB) {
    extern __shared__ __align__(16) char smem[];
    const uint32_t sb = smem_u32(smem);
    const uint32_t data = sb + 1024;
    const int tid = threadIdx.x, lane = tid & 31, wid = tid >> 5;
    const int b = blockIdx.z, c0 = blockIdx.y * 128, m0 = blockIdx.x * 256;

    if (tid == 0) {
        for (int s = 0; s < STAGES; s++) {
            MBAR_INIT(sb + 16 + 16 * s, 1);   // full: tx-based
            MBAR_INIT(sb + 24 + 16 * s, 8);   // empty: 8 consumer-warp arrivals
        }
    }
    __syncthreads();

    const int NCH = NN / 64;  // 64

    if (wid == 8) {
        if (lane == 0) {
            for (int kc = 0; kc < NCH; kc++) {
                int slot = kc & 3;
                if (kc >= STAGES) mbar_wait(sb + 24 + 16 * slot, ((kc >> 2) - 1) & 1);
                MBAR_EXPECT(sb + 16 + 16 * slot, STGB);
                tma3d(data + slot * STGB, &tmA, kc * 64, c0, b, sb + 16 + 16 * slot);
                tma3d(data + slot * STGB + BOFF, &tmB, kc * 64, m0, b, sb + 16 + 16 * slot);
            }
        }
        return;
    }

    const int wm = (wid & 1) * 64, wn = (wid >> 1) * 64;
    float acc[4][8][4];
#pragma unroll
    for (int i = 0; i < 4; i++)
#pragma unroll
        for (int j = 0; j < 8; j++)
#pragma unroll
            for (int k = 0; k < 4; k++) acc[i][j][k] = 0.f;

    uint32_t a[2][4][4], bf[2][4][4];

    for (int kc = 0; kc < NCH; kc++) {
        int slot = kc & 3;
        mbar_wait(sb + 16 + 16 * slot, (kc >> 2) & 1);
        uint32_t Ab = data + slot * STGB;
        uint32_t Bb = Ab + BOFF;

        // load kk=0 frags into buffer 0
        {
            uint32_t cb = (uint32_t)(((lane >> 4) * 8) * 2);
#pragma unroll
            for (int mi = 0; mi < 4; mi++) {
                int r = wm + mi * 16 + (lane & 15);
                ldsm_x4(a[0][mi][0], a[0][mi][1], a[0][mi][2], a[0][mi][3],
                        Ab + (uint32_t)(r * 128) + ((((uint32_t)(r & 7)) << 4) ^ cb));
            }
#pragma unroll
            for (int ni = 0; ni < 4; ni++) {
                int r = wn + ni * 16 + (lane & 15);
                ldsm_x4(bf[0][ni][0], bf[0][ni][1], bf[0][ni][2], bf[0][ni][3],
                        Bb + (uint32_t)(r * 128) + ((((uint32_t)(r & 7)) << 4) ^ cb));
            }
        }
#pragma unroll
        for (int kk = 0; kk < 4; kk++) {
            int cur = kk & 1;
            if (kk < 3) {  // prefetch kk+1 frags into the other buffer
                int nxt = cur ^ 1;
                uint32_t cb = (uint32_t)(((kk + 1) * 16 + (lane >> 4) * 8) * 2);
#pragma unroll
                for (int mi = 0; mi < 4; mi++) {
                    int r = wm + mi * 16 + (lane & 15);
                    ldsm_x4(a[nxt][mi][0], a[nxt][mi][1], a[nxt][mi][2], a[nxt][mi][3],
                            Ab + (uint32_t)(r * 128) + ((((uint32_t)(r & 7)) << 4) ^ cb));
                }
#pragma unroll
                for (int ni = 0; ni < 4; ni++) {
                    int r = wn + ni * 16 + (lane & 15);
                    ldsm_x4(bf[nxt][ni][0], bf[nxt][ni][1], bf[nxt][ni][2], bf[nxt][ni][3],
                            Bb + (uint32_t)(r * 128) + ((((uint32_t)(r & 7)) << 4) ^ cb));
                }
            }
#pragma unroll
            for (int mi = 0; mi < 4; mi++)
#pragma unroll
                for (int ni = 0; ni < 4; ni++) {
                    mma_16816(acc[mi][2 * ni + 0], a[cur][mi], bf[cur][ni][0], bf[cur][ni][2]);
                    mma_16816(acc[mi][2 * ni + 1], a[cur][mi], bf[cur][ni][1], bf[cur][ni][3]);
                }
            if (kk == 2 && lane == 0) MBAR_ARRIVE(sb + 24 + 16 * slot);
        }
    }

    // epilogue: bf16 matbf
    __nv_bfloat16* Mo = g_matbf + (size_t)b * CH * CH;
#pragma unroll
    for (int mi = 0; mi < 4; mi++) {
        int r = c0 + wm + mi * 16 + (lane >> 2);
#pragma unroll
        for (int g = 0; g < 8; g++) {
            int col = m0 + wn + g * 8 + (lane & 3) * 2;
            *(__nv_bfloat162*)(Mo + (size_t)r * CH + col) =
                __floats2bfloat162_rn(acc[mi][g][0], acc[mi][g][1]);
            *(__nv_bfloat162*)(Mo + (size_t)(r + 8) * CH + col) =
                __floats2bfloat162_rn(acc[mi][g][2], acc[mi][g][3]);
        }
    }
}

// ---------------- kernel 4: GEMM2 + fused epilogue ----------------
// CTA tile 128(c) x 256(n), K=512.  288 threads: 8 consumers + 1 TMA producer.
__global__ void __launch_bounds__(GTHREADS, 1) gemm2_tc(const __grid_constant__ CUtensorMap tmA,
                                                        const __grid_constant__ CUtensorMap tmB,
                                                        const float* __restrict__ x,
                                                        const float* __restrict__ gamma,
                                                        float* __restrict__ out) {
    extern __shared__ __align__(16) char smem[];
    const uint32_t sb = smem_u32(smem);
    const uint32_t data = sb + 1024;
    const int tid = threadIdx.x, lane = tid & 31, wid = tid >> 5;
    const int b = blockIdx.z, c0 = blockIdx.y * 128, n0 = blockIdx.x * 256;

    if (tid == 0) {
        for (int s = 0; s < STAGES; s++) {
            MBAR_INIT(sb + 16 + 16 * s, 1);
            MBAR_INIT(sb + 24 + 16 * s, 8);
        }
    }
    __syncthreads();

    const int NCH = CH / 64;  // 8

    if (wid == 8) {
        if (lane == 0) {
            for (int kc = 0; kc < NCH; kc++) {
                int slot = kc & 3;
                if (kc >= STAGES) mbar_wait(sb + 24 + 16 * slot, ((kc >> 2) - 1) & 1);
                MBAR_EXPECT(sb + 16 + 16 * slot, STGB);
                tma3d(data + slot * STGB, &tmA, kc * 64, c0, b, sb + 16 + 16 * slot);
#pragma unroll
                for (int sub = 0; sub < 4; sub++)
                    tma3d(data + slot * STGB + BOFF + sub * 8192, &tmB, n0 + sub * 64, kc * 64, b,
                          sb + 16 + 16 * slot);
            }
        }
        return;
    }

    const int wm = (wid & 1) * 64, wn = (wid >> 1) * 64;
    float acc[4][8][4];
#pragma unroll
    for (int i = 0; i < 4; i++)
#pragma unroll
        for (int j = 0; j < 8; j++)
#pragma unroll
            for (int k = 0; k < 4; k++) acc[i][j][k] = 0.f;

    uint32_t a[2][4][4], bf[2][4][4];

    for (int kc = 0; kc < NCH; kc++) {
        int slot = kc & 3;
        mbar_wait(sb + 16 + 16 * slot, (kc >> 2) & 1);
        uint32_t Ab = data + slot * STGB;
        uint32_t Bsub = Ab + BOFF + (uint32_t)(wn >> 6) * 8192;

        {
            uint32_t cb = (uint32_t)(((lane >> 4) * 8) * 2);
#pragma unroll
            for (int mi = 0; mi < 4; mi++) {
                int r = wm + mi * 16 + (lane & 15);
                ldsm_x4(a[0][mi][0], a[0][mi][1], a[0][mi][2], a[0][mi][3],
                        Ab + (uint32_t)(r * 128) + ((((uint32_t)(r & 7)) << 4) ^ cb));
            }
            int kr = (lane & 15);
            uint32_t brow = Bsub + (uint32_t)(kr * 128);
            uint32_t swz = ((uint32_t)(kr & 7)) << 4;
#pragma unroll
            for (int ni = 0; ni < 4; ni++) {
                uint32_t colb = (uint32_t)((ni * 16 + (lane >> 4) * 8) * 2);
                ldsm_x4_t(bf[0][ni][0], bf[0][ni][1], bf[0][ni][2], bf[0][ni][3], brow + (swz ^ colb));
            }
        }
#pragma unroll
        for (int kk = 0; kk < 4; kk++) {
            int cur = kk & 1;
            if (kk < 3) {
                int nxt = cur ^ 1;
                uint32_t cb = (uint32_t)(((kk + 1) * 16 + (lane >> 4) * 8) * 2);
#pragma unroll
                for (int mi = 0; mi < 4; mi++) {
                    int r = wm + mi * 16 + (lane & 15);
                    ldsm_x4(a[nxt][mi][0], a[nxt][mi][1], a[nxt][mi][2], a[nxt][mi][3],
                            Ab + (uint32_t)(r * 128) + ((((uint32_t)(r & 7)) << 4) ^ cb));
                }
                int kr = (kk + 1) * 16 + (lane & 15);
                uint32_t brow = Bsub + (uint32_t)(kr * 128);
                uint32_t swz = ((uint32_t)(kr & 7)) << 4;
#pragma unroll
                for (int ni = 0; ni < 4; ni++) {
                    uint32_t colb = (uint32_t)((ni * 16 + (lane >> 4) * 8) * 2);
                    ldsm_x4_t(bf[nxt][ni][0], bf[nxt][ni][1], bf[nxt][ni][2], bf[nxt][ni][3],
                              brow + (swz ^ colb));
                }
            }
#pragma unroll
            for (int mi = 0; mi < 4; mi++)
#pragma unroll
                for (int ni = 0; ni < 4; ni++) {
                    mma_16816(acc[mi][2 * ni + 0], a[cur][mi], bf[cur][ni][0], bf[cur][ni][1]);
                    mma_16816(acc[mi][2 * ni + 1], a[cur][mi], bf[cur][ni][2], bf[cur][ni][3]);
                }
            if (kk == 2 && lane == 0) MBAR_ARRIVE(sb + 24 + 16 * slot);
        }
    }

    // fused epilogue
    const float gam = gamma[0];
    const float* vsum = g_vsum + b * NN;
    const float* sqin = g_sqin + b * NN;
    const float* tl = g_tailor + b * CH;
    const size_t base = (size_t)b * CH * NN;
#pragma unroll
    for (int mi = 0; mi < 4; mi++) {
        int r = c0 + wm + mi * 16 + (lane >> 2);
        float t0 = gam * tl[r];
        float t1 = gam * tl[r + 8];
#pragma unroll
        for (int g = 0; g < 8; g++) {
            int col = n0 + wn + g * 8 + (lane & 3) * 2;
            float2 vs2 = *(const float2*)(vsum + col);
            float2 sq2 = *(const float2*)(sqin + col);
            size_t i0 = base + (size_t)r * NN + col;
            float2 xv = *(const float2*)(x + i0);
            float2 o;
            o.x = xv.x + t0 * (vs2.x + sq2.x * acc[mi][g][0]);
            o.y = xv.y + t0 * (vs2.y + sq2.y * acc[mi][g][1]);
            *(float2*)(out + i0) = o;
            size_t i1 = i0 + (size_t)8 * NN;
            xv = *(const float2*)(x + i1);
            o.x = xv.x + t1 * (vs2.x + sq2.x * acc[mi][g][2]);
            o.y = xv.y + t1 * (vs2.y + sq2.y * acc[mi][g][3]);
            *(float2*)(out + i1) = o;
        }
    }
}

// ---------------- host: tensor maps + launch ----------------
typedef CUresult (*TmapEncodeFn)(CUtensorMap*, CUtensorMapDataType, cuuint32_t, void*,
                                 const cuuint64_t*, const cuuint64_t*, const cuuint32_t*,
                                 const cuuint32_t*, CUtensorMapInterleave, CUtensorMapSwizzle,
                                 CUtensorMapL2promotion, CUtensorMapFloatOOBfill);

static void mk_tmap(TmapEncodeFn enc, CUtensorMap* tm, void* base,
                    unsigned long long d0, unsigned long long d1, unsigned long long d2,
                    unsigned long long s1, unsigned long long s2,
                    unsigned b0, unsigned b1) {
    cuuint64_t dims[3] = {d0, d1, d2};
    cuuint64_t str[2] = {s1, s2};
    cuuint32_t box[3] = {b0, b1, 1};
    cuuint32_t es[3] = {1, 1, 1};
    enc(tm, CU_TENSOR_MAP_DATA_TYPE_BFLOAT16, 3, base, dims, str, box, es,
        CU_TENSOR_MAP_INTERLEAVE_NONE, CU_TENSOR_MAP_SWIZZLE_128B,
        CU_TENSOR_MAP_L2_PROMOTION_L2_128B, CU_TENSOR_MAP_FLOAT_OOB_FILL_NONE);
}

extern "C" void kernel_launch(void* const* d_in, const int* in_sizes, int n_in,
                              void* d_out, int out_size) {
    (void)in_sizes; (void)n_in; (void)out_size;
    const float* x = (const float*)d_in[0];
    const float* gamma = (const float*)d_in[1];
    float* out = (float*)d_out;

    void* fp = nullptr;
    cudaDriverEntryPointQueryResult qr;
    cudaGetDriverEntryPointByVersion("cuTensorMapEncodeTiled", &fp, 12000, cudaEnableDefault, &qr);
    TmapEncodeFn enc = (TmapEncodeFn)fp;

    void *pVs = nullptr, *pM = nullptr;
    cudaGetSymbolAddress(&pVs, g_Vs);
    cudaGetSymbolAddress(&pM, g_matbf);

    CUtensorMap tA1, tB1, tA2, tB2;
    mk_tmap(enc, &tA1, pVs, NN, CH, BATCH, (unsigned long long)NN * 2,
            (unsigned long long)CH * NN * 2, 64, 128);
    mk_tmap(enc, &tB1, pVs, NN, CH, BATCH, (unsigned long long)NN * 2,
            (unsigned long long)CH * NN * 2, 64, 256);
    mk_tmap(enc, &tA2, pM, CH, CH, BATCH, (unsigned long long)CH * 2,
            (unsigned long long)CH * CH * 2, 64, 128);
    mk_tmap(enc, &tB2, pVs, NN, CH, BATCH, (unsigned long long)NN * 2,
            (unsigned long long)CH * NN * 2, 64, 64);

    cudaFuncSetAttribute(stats_kernel, cudaFuncAttributeMaxDynamicSharedMemorySize, STATS_SMEM);
    cudaFuncSetAttribute(gemm1_tc, cudaFuncAttributeMaxDynamicSharedMemorySize, GSMEM);
    cudaFuncSetAttribute(gemm2_tc, cudaFuncAttributeMaxDynamicSharedMemorySize, GSMEM);

    stats_kernel<<<dim3(NN / SN, BATCH), 256, STATS_SMEM>>>(x);
    gemm1_tc<<<dim3(2, 4, BATCH), GTHREADS, GSMEM>>>(tA1, tB1);
    tailor_reduce<<<BATCH, 512>>>();
    gemm2_tc<<<dim3(16, 4, BATCH), GTHREADS, GSMEM>>>(tA2, tB2, x, gamma, out);
}